// round 6
// baseline (speedup 1.0000x reference)
#include <cuda_runtime.h>
#include <math.h>

// Problem constants
#define BB   128
#define NS   128
#define NQ   512
#define DIN  256
#define DOUT 64

// d_out layout: mu | sig | nll
#define MU_N  ((long long)BB * NQ * DOUT)            // 4,194,304
#define SIG_N ((long long)BB * NQ * DOUT * DOUT)     // 134,217,728

// ---------------- scratch (static device globals; no allocation) ----------------
#define OFF_SP     0LL
#define OFF_MPN    65536LL
#define OFF_SINV   81920LL
#define OFF_S      8470528LL
#define OFF_LA     16859136LL
#define OFF_LS     18956288LL
#define OFF_AI     21053440LL
#define OFF_X      23150592LL
#define OFF_SC     25247744LL
#define OFF_Y      27344896LL
#define OFF_RHS    29442048LL
#define OFF_M      31539200LL
#define OFF_T1     33636352LL
#define OFF_SPREAD 50413568LL
#define BUF_TOTAL  50479104LL

__device__ float  g_buf[BUF_TOTAL];
__device__ double g_nll_acc;

// ---------------- generic batched SGEMM ----------------
// C[b] = alpha * op(A[b]) @ op(B[b]) + (Dd ? Dd[b] : 0)
// op(A) is MxK. tA==0: A is MxK (elem (m,k) at A[m*lda+k]); tA==1: A is KxM (elem at A[k*lda+m]).
// op(B) is KxN. tB==0: B is KxN; tB==1: B is NxK (elem (k,n) at B[n*ldb+k]).
// Requires M,N multiples of 64, K multiple of 16, all lds multiples of 4.
__global__ void sgemm_kernel(
    int M, int N, int K,
    const float* __restrict__ A, int lda, long long sA, int tA,
    const float* __restrict__ B, int ldb, long long sB, int tB,
    const float* __restrict__ Dd, int ldd, long long sD,
    float alpha,
    float* __restrict__ C, int ldc, long long sC)
{
    __shared__ float As[16][68];
    __shared__ float Bs[16][68];

    int b  = blockIdx.z;
    const float* Ab = A + (long long)b * sA;
    const float* Bb = B + (long long)b * sB;
    float*       Cb = C + (long long)b * sC;

    int m0 = blockIdx.y * 64;
    int n0 = blockIdx.x * 64;
    int tx = threadIdx.x;   // 0..15
    int ty = threadIdx.y;   // 0..15
    int tid = ty * 16 + tx;

    float acc[4][4];
#pragma unroll
    for (int i = 0; i < 4; i++)
#pragma unroll
        for (int j = 0; j < 4; j++) acc[i][j] = 0.f;

    for (int k0 = 0; k0 < K; k0 += 16) {
        // ---- load A tile into As[k][m] ----
        if (tA == 0) {
            int m  = tid >> 2;
            int kq = (tid & 3) * 4;
            float4 v = *(const float4*)(Ab + (long long)(m0 + m) * lda + k0 + kq);
            As[kq + 0][m] = v.x; As[kq + 1][m] = v.y;
            As[kq + 2][m] = v.z; As[kq + 3][m] = v.w;
        } else {
            int k  = tid >> 4;
            int mq = (tid & 15) * 4;
            float4 v = *(const float4*)(Ab + (long long)(k0 + k) * lda + m0 + mq);
            *(float4*)&As[k][mq] = v;
        }
        // ---- load B tile into Bs[k][n] ----
        if (tB == 0) {
            int k  = tid >> 4;
            int nq = (tid & 15) * 4;
            float4 v = *(const float4*)(Bb + (long long)(k0 + k) * ldb + n0 + nq);
            *(float4*)&Bs[k][nq] = v;
        } else {
            int n  = tid >> 2;
            int kq = (tid & 3) * 4;
            float4 v = *(const float4*)(Bb + (long long)(n0 + n) * ldb + k0 + kq);
            Bs[kq + 0][n] = v.x; Bs[kq + 1][n] = v.y;
            Bs[kq + 2][n] = v.z; Bs[kq + 3][n] = v.w;
        }
        __syncthreads();

#pragma unroll
        for (int k = 0; k < 16; k++) {
            float4 a  = *(const float4*)&As[k][ty * 4];
            float4 bb = *(const float4*)&Bs[k][tx * 4];
            acc[0][0] += a.x * bb.x; acc[0][1] += a.x * bb.y; acc[0][2] += a.x * bb.z; acc[0][3] += a.x * bb.w;
            acc[1][0] += a.y * bb.x; acc[1][1] += a.y * bb.y; acc[1][2] += a.y * bb.z; acc[1][3] += a.y * bb.w;
            acc[2][0] += a.z * bb.x; acc[2][1] += a.z * bb.y; acc[2][2] += a.z * bb.z; acc[2][3] += a.z * bb.w;
            acc[3][0] += a.w * bb.x; acc[3][1] += a.w * bb.y; acc[3][2] += a.w * bb.z; acc[3][3] += a.w * bb.w;
        }
        __syncthreads();
    }

    // ---- epilogue ----
#pragma unroll
    for (int i = 0; i < 4; i++) {
        int m = m0 + ty * 4 + i;
        float4 o;
        o.x = alpha * acc[i][0];
        o.y = alpha * acc[i][1];
        o.z = alpha * acc[i][2];
        o.w = alpha * acc[i][3];
        if (Dd) {
            float4 d = *(const float4*)(Dd + (long long)b * sD + (long long)m * ldd + n0 + tx * 4);
            o.x += d.x; o.y += d.y; o.z += d.z; o.w += d.w;
        }
        *(float4*)(Cb + (long long)m * ldc + n0 + tx * 4) = o;
    }
}

// ---------------- per-CTA smem Cholesky + triangular inverse (n=128) ----------------
// Input: SPD 128x128 (row stride ldin, batch stride strideIn). Output: Linv (128x128, row-major)
// such that A^{-1} = Linv^T Linv.
__global__ void chol_linv_kernel(const float* __restrict__ in, int ldin, long long strideIn,
                                 float* __restrict__ Lout)
{
    extern __shared__ float sh[];
    float* sL  = sh;                // [128][129]
    float* sX  = sh + 128 * 129;    // [128][129]
    float* rd  = sh + 2 * 128 * 129;// [128]
    float* sdi = rd + 128;          // [1]
#define SL(i,k) sL[(i) * 129 + (k)]
#define SX(i,k) sX[(i) * 129 + (k)]

    int b   = blockIdx.x;
    int tid = threadIdx.x;          // 0..127
    const float* A = in + (long long)b * strideIn;
    float* out = Lout + (long long)b * (128 * 128);

    for (int idx = tid; idx < 128 * 128; idx += 128) {
        int r = idx >> 7, c = idx & 127;
        SL(r, c) = A[(long long)r * ldin + c];
    }
    __syncthreads();

    // left-looking Cholesky (lower)
    for (int j = 0; j < 128; j++) {
        float t = 0.f;
        if (tid >= j) {
            t = SL(tid, j);
            float a0 = 0.f, a1 = 0.f, a2 = 0.f, a3 = 0.f;
            int k = 0;
            for (; k + 3 < j; k += 4) {
                a0 += SL(tid, k)     * SL(j, k);
                a1 += SL(tid, k + 1) * SL(j, k + 1);
                a2 += SL(tid, k + 2) * SL(j, k + 2);
                a3 += SL(tid, k + 3) * SL(j, k + 3);
            }
            for (; k < j; k++) a0 += SL(tid, k) * SL(j, k);
            t -= (a0 + a1) + (a2 + a3);
        }
        if (tid == j) {
            float d = sqrtf(t);
            SL(j, j) = d;
            sdi[0] = 1.f / d;
        }
        __syncthreads();
        if (tid > j) SL(tid, j) = t * sdi[0];
        __syncthreads();
    }

    rd[tid] = 1.f / SL(tid, tid);
    __syncthreads();

    // column-parallel triangular inverse: sX = L^{-1}
    {
        int c = tid;
        for (int i = 0; i < c; i++) SX(i, c) = 0.f;
        SX(c, c) = rd[c];
        for (int i = c + 1; i < 128; i++) {
            float a0 = 0.f, a1 = 0.f, a2 = 0.f, a3 = 0.f;
            int k = c;
            for (; k + 3 < i; k += 4) {
                a0 += SL(i, k)     * SX(k, c);
                a1 += SL(i, k + 1) * SX(k + 1, c);
                a2 += SL(i, k + 2) * SX(k + 2, c);
                a3 += SL(i, k + 3) * SX(k + 3, c);
            }
            for (; k < i; k++) a0 += SL(i, k) * SX(k, c);
            SX(i, c) = -rd[i] * ((a0 + a1) + (a2 + a3));
        }
    }
    __syncthreads();

    for (int idx = tid; idx < 128 * 128; idx += 128) {
        int r = idx >> 7, c = idx & 127;
        out[idx] = SX(r, c);
    }
#undef SL
#undef SX
}

// ---------------- TR/BL assembly: S_TR = -Y, S_BL = -Y^T ----------------
__global__ void trbl_kernel(const float* __restrict__ Y, float* __restrict__ S)
{
    int idx = blockIdx.x * blockDim.x + threadIdx.x;
    if (idx >= 128 * 16384) return;
    int b  = idx >> 14;
    int ij = idx & 16383;
    int i2 = ij >> 7, j2 = ij & 127;
    float v = -Y[idx];
    float* Sb = S + (long long)b * 65536;
    Sb[i2 * 256 + 128 + j2] = v;        // TR[i][j]
    Sb[(128 + j2) * 256 + i2] = v;      // BL[j][i] = TR[i][j]
}

// ---------------- spread = 1 + rowdot(T1, phiQ) ----------------
__global__ void spread_kernel(const float* __restrict__ T1, const float* __restrict__ phiQ,
                              float* __restrict__ spread)
{
    int gw   = (blockIdx.x * blockDim.x + threadIdx.x) >> 5;
    int lane = threadIdx.x & 31;
    if (gw >= BB * NQ) return;
    const float* t = T1   + (long long)gw * DIN;
    const float* p = phiQ + (long long)gw * DIN;
    float s = 0.f;
    for (int k = lane; k < DIN; k += 32) s += t[k] * p[k];
#pragma unroll
    for (int o = 16; o; o >>= 1) s += __shfl_xor_sync(0xFFFFFFFFu, s, o);
    if (lane == 0) spread[gw] = 1.f + s;
}

// ---------------- sig fill (diagonal [B,Q,64,64]) ----------------
__global__ void sigfill_kernel(float* __restrict__ sig, const float* __restrict__ spread,
                               const float* __restrict__ sig_eps)
{
    long long i = (long long)blockIdx.x * blockDim.x + threadIdx.x;   // float4 index
    const long long NV = SIG_N / 4;
    if (i >= NV) return;
    long long pos = i * 4;
    int bq = (int)(pos >> 12);
    int k  = (int)(pos & 4095);
    int r  = k >> 6;
    int c  = k & 63;
    float sf = spread[bq] * sig_eps[0];
    float4 o;
    o.x = (c     == r) ? sf : 0.f;
    o.y = (c + 1 == r) ? sf : 0.f;
    o.z = (c + 2 == r) ? sf : 0.f;
    o.w = (c + 3 == r) ? sf : 0.f;
    *(float4*)(sig + pos) = o;
}

// ---------------- nll ----------------
__global__ void nll_init_kernel(double* acc) { *acc = 0.0; }

__global__ void nll_kernel(const float* __restrict__ yq, const float* __restrict__ mu,
                           const float* __restrict__ spread, const float* __restrict__ sig_eps,
                           double* __restrict__ acc)
{
    int bq = blockIdx.x * blockDim.x + threadIdx.x;   // 65536 threads total
    float se = sig_eps[0];
    float sp = spread[bq];
    const float* y = yq + (long long)bq * DOUT;
    const float* m = mu + (long long)bq * DOUT;
    float q = 0.f;
#pragma unroll
    for (int d = 0; d < DOUT; d++) { float r = y[d] - m[d]; q += r * r; }
    float val = (float)DOUT * (logf(sp) + logf(se)) + q / (sp * se);

    __shared__ double s[256];
    s[threadIdx.x] = (double)val;
    __syncthreads();
    for (int o = 128; o; o >>= 1) {
        if (threadIdx.x < o) s[threadIdx.x] += s[threadIdx.x + o];
        __syncthreads();
    }
    if (threadIdx.x == 0) atomicAdd(acc, s[0]);
}

__global__ void nll_final_kernel(const double* __restrict__ acc, float* __restrict__ out)
{
    out[0] = (float)(acc[0] / (double)(BB * NQ));
}

// ---------------- launch ----------------
extern "C" void kernel_launch(void* const* d_in, const int* in_sizes, int n_in,
                              void* d_out, int out_size)
{
    const float* phiS = (const float*)d_in[0];   // [128,128,256]
    const float* yS   = (const float*)d_in[1];   // [128,128,64]
    const float* phiQ = (const float*)d_in[2];   // [128,512,256]
    const float* yQ   = (const float*)d_in[3];   // [128,512,64]
    const float* mpr  = (const float*)d_in[4];   // [256,64]
    const float* asym = (const float*)d_in[5];   // [256,256]
    const float* se   = (const float*)d_in[6];   // [1]
    float* out = (float*)d_out;

    float*  buf  = nullptr;
    double* nacc = nullptr;
    cudaGetSymbolAddress((void**)&buf,  g_buf);
    cudaGetSymbolAddress((void**)&nacc, g_nll_acc);

    float* Sp   = buf + OFF_SP;
    float* Mpn  = buf + OFF_MPN;
    float* Sinv = buf + OFF_SINV;
    float* Smat = buf + OFF_S;
    float* LA   = buf + OFF_LA;
    float* LS   = buf + OFF_LS;
    float* Ai   = buf + OFF_AI;
    float* Xm   = buf + OFF_X;
    float* Sc   = buf + OFF_SC;
    float* Ym   = buf + OFF_Y;
    float* Rhs  = buf + OFF_RHS;
    float* Mm   = buf + OFF_M;
    float* T1   = buf + OFF_T1;
    float* Spr  = buf + OFF_SPREAD;

    float* mu_out  = out;
    float* sig_out = out + MU_N;
    float* nll_out = out + MU_N + SIG_N;

    const int CHOL_SMEM = (2 * 128 * 129 + 128 + 4) * 4;
    cudaFuncSetAttribute(chol_linv_kernel, cudaFuncAttributeMaxDynamicSharedMemorySize, CHOL_SMEM);

    dim3 blk(16, 16);

    nll_init_kernel<<<1, 1>>>(nacc);

    // Sp = asym @ asym^T          (prior precision, alpha=1)
    sgemm_kernel<<<dim3(4, 4, 1), blk>>>(256, 256, 256,
        asym, 256, 0, 0,  asym, 256, 0, 1,  nullptr, 0, 0, 1.f,  Sp, 256, 0);
    // Mpn = Sp @ m_prior
    sgemm_kernel<<<dim3(1, 4, 1), blk>>>(256, 64, 256,
        Sp, 256, 0, 0,  mpr, 64, 0, 0,  nullptr, 0, 0, 1.f,  Mpn, 64, 0);
    // Sinv[b] = phiS^T phiS + Sp
    sgemm_kernel<<<dim3(4, 4, BB), blk>>>(256, 256, 128,
        phiS, 256, 32768, 1,  phiS, 256, 32768, 0,  Sp, 256, 0, 1.f,  Sinv, 256, 65536);
    // Rhs[b] = phiS^T yS + Mpn
    sgemm_kernel<<<dim3(1, 4, BB), blk>>>(256, 64, 128,
        phiS, 256, 32768, 1,  yS, 64, 8192, 0,  Mpn, 64, 0, 1.f,  Rhs, 64, 16384);

    // LA = chol-inv of A-block (top-left 128x128 of Sinv)
    chol_linv_kernel<<<BB, 128, CHOL_SMEM>>>(Sinv, 256, 65536, LA);
    // Ai = LA^T LA  (= A^{-1})
    sgemm_kernel<<<dim3(2, 2, BB), blk>>>(128, 128, 128,
        LA, 128, 16384, 1,  LA, 128, 16384, 0,  nullptr, 0, 0, 1.f,  Ai, 128, 16384);
    // X = Ai @ Bblk
    sgemm_kernel<<<dim3(2, 2, BB), blk>>>(128, 128, 128,
        Ai, 128, 16384, 0,  Sinv + 128, 256, 65536, 0,  nullptr, 0, 0, 1.f,  Xm, 128, 16384);
    // Sc = Dblk - Bblk^T X
    sgemm_kernel<<<dim3(2, 2, BB), blk>>>(128, 128, 128,
        Sinv + 128, 256, 65536, 1,  Xm, 128, 16384, 0,
        Sinv + 128 * 256 + 128, 256, 65536, -1.f,  Sc, 128, 16384);
    // LS = chol-inv of Sc
    chol_linv_kernel<<<BB, 128, CHOL_SMEM>>>(Sc, 128, 16384, LS);
    // S_BR = LS^T LS  (= Sc^{-1})
    sgemm_kernel<<<dim3(2, 2, BB), blk>>>(128, 128, 128,
        LS, 128, 16384, 1,  LS, 128, 16384, 0,  nullptr, 0, 0, 1.f,
        Smat + 128 * 256 + 128, 256, 65536);
    // Y = X @ S_BR
    sgemm_kernel<<<dim3(2, 2, BB), blk>>>(128, 128, 128,
        Xm, 128, 16384, 0,  Smat + 128 * 256 + 128, 256, 65536, 0,
        nullptr, 0, 0, 1.f,  Ym, 128, 16384);
    // S_TL = Ai + Y @ X^T
    sgemm_kernel<<<dim3(2, 2, BB), blk>>>(128, 128, 128,
        Ym, 128, 16384, 0,  Xm, 128, 16384, 1,  Ai, 128, 16384, 1.f,  Smat, 256, 65536);
    // S_TR = -Y, S_BL = -Y^T
    trbl_kernel<<<(128 * 16384 + 255) / 256, 256>>>(Ym, Smat);

    // m = S @ Rhs
    sgemm_kernel<<<dim3(1, 4, BB), blk>>>(256, 64, 256,
        Smat, 256, 65536, 0,  Rhs, 64, 16384, 0,  nullptr, 0, 0, 1.f,  Mm, 64, 16384);
    // mu = phiQ @ m   -> d_out
    sgemm_kernel<<<dim3(1, 8, BB), blk>>>(512, 64, 256,
        phiQ, 256, 131072, 0,  Mm, 64, 16384, 0,  nullptr, 0, 0, 1.f,  mu_out, 64, 32768);
    // T1 = phiQ @ S
    sgemm_kernel<<<dim3(4, 8, BB), blk>>>(512, 256, 256,
        phiQ, 256, 131072, 0,  Smat, 256, 65536, 0,  nullptr, 0, 0, 1.f,  T1, 256, 131072);
    // spread = 1 + rowdot(T1, phiQ)
    spread_kernel<<<(BB * NQ * 32) / 256, 256>>>(T1, phiQ, Spr);
    // sig (diagonal) fill
    sigfill_kernel<<<(unsigned int)(SIG_N / 4 / 256), 256>>>(sig_out, Spr, se);
    // nll
    nll_kernel<<<(BB * NQ) / 256, 256>>>(yQ, mu_out, Spr, se, nacc);
    nll_final_kernel<<<1, 1>>>(nacc, nll_out);

    (void)in_sizes; (void)n_in; (void)out_size;
}